// round 6
// baseline (speedup 1.0000x reference)
#include <cuda_runtime.h>
#include <cuda_bf16.h>
#include <cstdint>

#define MARGIN   0.3f
#define NEG_FILL 1e9f
#define MAXB 8192
#define MAXE (4096 * 256)

#define TM 128
#define KC 64
#define KST 72                       // row stride elems (144B): ldsm + cp.async friendly
#define TILE_B (128 * 144)           // 18432
#define STAGE_B (4 * TILE_B)         // 73728

// ---- device scratch (allocation-free rule) ----
__device__ __align__(16) __nv_bfloat16 g_hi[MAXE];
__device__ __align__(16) __nv_bfloat16 g_lo[MAXE];
__device__ float g_sq[MAXB];
__device__ int   g_hp[MAXB];
__device__ int   g_hn[MAXB];

// ================= prep: split + norms + init, vectorized =================
__global__ void prep_kernel(const float* __restrict__ E, int B, int D) {
    int t = threadIdx.x;
    int rloc = t >> 6;
    int c = t & 63;
    int row = blockIdx.x * 4 + rloc;
    const float4* src = (const float4*)(E + (size_t)row * D) + c;
    float4 x = *src;

    __nv_bfloat16 h0 = __float2bfloat16(x.x), h1 = __float2bfloat16(x.y);
    __nv_bfloat16 h2 = __float2bfloat16(x.z), h3 = __float2bfloat16(x.w);
    __nv_bfloat16 l0 = __float2bfloat16(x.x - __bfloat162float(h0));
    __nv_bfloat16 l1 = __float2bfloat16(x.y - __bfloat162float(h1));
    __nv_bfloat16 l2 = __float2bfloat16(x.z - __bfloat162float(h2));
    __nv_bfloat16 l3 = __float2bfloat16(x.w - __bfloat162float(h3));

    __nv_bfloat162* ph = (__nv_bfloat162*)(g_hi + (size_t)row * D);
    __nv_bfloat162* pl = (__nv_bfloat162*)(g_lo + (size_t)row * D);
    ph[c * 2]     = __nv_bfloat162(h0, h1);
    ph[c * 2 + 1] = __nv_bfloat162(h2, h3);
    pl[c * 2]     = __nv_bfloat162(l0, l1);
    pl[c * 2 + 1] = __nv_bfloat162(l2, l3);

    float s = fmaf(x.x, x.x, fmaf(x.y, x.y, fmaf(x.z, x.z, x.w * x.w)));
    #pragma unroll
    for (int o = 16; o > 0; o >>= 1) s += __shfl_xor_sync(0xffffffffu, s, o);
    __shared__ float sm[8];
    if ((t & 31) == 0) sm[t >> 5] = s;
    __syncthreads();
    if (t < 4) {
        int r = blockIdx.x * 4 + t;
        g_sq[r] = sm[2 * t] + sm[2 * t + 1];
        g_hp[r] = __float_as_int(-1.0f);
        g_hn[r] = __float_as_int(NEG_FILL);
    }
}

// ================= mma.sync helpers =================
__device__ __forceinline__ void cp16(uint32_t s, const void* g) {
    asm volatile("cp.async.cg.shared.global [%0], [%1], 16;\n" :: "r"(s), "l"(g));
}
__device__ __forceinline__ void ldsm4(unsigned r[4], const __nv_bfloat16* p) {
    unsigned a = (unsigned)__cvta_generic_to_shared(p);
    asm volatile("ldmatrix.sync.aligned.m8n8.x4.shared.b16 {%0,%1,%2,%3}, [%4];"
                 : "=r"(r[0]), "=r"(r[1]), "=r"(r[2]), "=r"(r[3]) : "r"(a));
}
__device__ __forceinline__ void mma_bf16(float c[4], const unsigned a[4], const unsigned* b) {
    asm volatile(
        "mma.sync.aligned.m16n8k16.row.col.f32.bf16.bf16.f32 "
        "{%0,%1,%2,%3}, {%4,%5,%6,%7}, {%8,%9}, {%0,%1,%2,%3};\n"
        : "+f"(c[0]), "+f"(c[1]), "+f"(c[2]), "+f"(c[3])
        : "r"(a[0]), "r"(a[1]), "r"(a[2]), "r"(a[3]), "r"(b[0]), "r"(b[1]));
}

// ================= main: 512-thread symmetric tiled MMA =================
extern __shared__ __nv_bfloat16 dynsmem[];

__global__ void __launch_bounds__(512, 1)
triplet_mma_sym(const int* __restrict__ L, int B, int D, int nt)
{
    const int tid = threadIdx.x;
    const int lane = tid & 31;
    const int w = tid >> 5;
    const int wr = w >> 2, wc = w & 3;       // 4x4 warp grid, 32x32 warp tiles
    const int gid = lane >> 2, tig = lane & 3;
    const int q8 = lane >> 3, r8 = lane & 7;

    // decode upper-triangular (bi <= bj) tile pair
    int u = blockIdx.x;
    float ntf = (float)nt + 0.5f;
    int bi = (int)(ntf - sqrtf(fmaxf(ntf * ntf - 2.0f * (float)u, 0.0f)));
    while (bi > 0 && (bi * nt - bi * (bi - 1) / 2) > u) bi--;
    while (((bi + 1) * nt - (bi + 1) * bi / 2) <= u) bi++;
    int bj = bi + (u - (bi * nt - bi * (bi - 1) / 2));
    const int i0 = bi * TM, j0 = bj * TM;

    __shared__ int s_hpi[TM], s_hni[TM], s_hpj[TM], s_hnj[TM];
    if (tid < TM) {
        s_hpi[tid] = __float_as_int(-1.0f); s_hni[tid] = __float_as_int(NEG_FILL);
        s_hpj[tid] = __float_as_int(-1.0f); s_hnj[tid] = __float_as_int(NEG_FILL);
    }

    float c[2][4][4];
    #pragma unroll
    for (int mf = 0; mf < 2; mf++)
        #pragma unroll
        for (int nf = 0; nf < 4; nf++)
            #pragma unroll
            for (int r = 0; r < 4; r++) c[mf][nf][r] = 0.0f;

    const uint32_t dsm_a = (uint32_t)__cvta_generic_to_shared(dynsmem);

    // stage fill: tiles {Ahi, Alo, Bhi, Blo}, each 128 rows x 64 elems (128B data, 144B stride)
    auto issue = [&](int kc, int st) {
        const int ch = tid & 7;           // 16B chunk
        const int rr = tid >> 3;          // 0..63
        #pragma unroll
        for (int q = 0; q < 8; q++) {
            const int tile = q >> 1;
            const int r = (q & 1) * 64 + rr;
            const __nv_bfloat16* gb = (tile == 0 || tile == 2) ? g_hi : g_lo;
            const int rowg = (tile < 2) ? (i0 + r) : (j0 + r);
            const void* gsrc = gb + (size_t)rowg * D + kc * KC + ch * 8;
            uint32_t dst = dsm_a + st * STAGE_B + tile * TILE_B + (uint32_t)(r * 144 + ch * 16);
            cp16(dst, gsrc);
        }
        asm volatile("cp.async.commit_group;");
    };

    issue(0, 0);

    const int NKC = D / KC;   // 4
    for (int kc = 0; kc < NKC; kc++) {
        const int cur = kc & 1;
        if (kc + 1 < NKC) {
            issue(kc + 1, cur ^ 1);
            asm volatile("cp.async.wait_group 1;");
        } else {
            asm volatile("cp.async.wait_group 0;");
        }
        __syncthreads();

        const __nv_bfloat16* sAhi = dynsmem + (cur * STAGE_B) / 2;
        const __nv_bfloat16* sAlo = sAhi + TILE_B / 2;
        const __nv_bfloat16* sBhi = sAhi + TILE_B;
        const __nv_bfloat16* sBlo = sAhi + 3 * TILE_B / 2;

        #pragma unroll
        for (int ks = 0; ks < KC / 16; ks++) {
            // B fragments (hi/lo), 2 ldsm4 each covering 2 nf groups
            unsigned bh[4][2], bl[4][2];
            #pragma unroll
            for (int h = 0; h < 2; h++) {
                int brow = wc * 32 + (2 * h + (q8 >> 1)) * 8 + r8;
                int bcol = ks * 16 + (q8 & 1) * 8;
                unsigned rh[4], rl[4];
                ldsm4(rh, &sBhi[brow * KST + bcol]);
                ldsm4(rl, &sBlo[brow * KST + bcol]);
                bh[2 * h][0] = rh[0]; bh[2 * h][1] = rh[1];
                bh[2 * h + 1][0] = rh[2]; bh[2 * h + 1][1] = rh[3];
                bl[2 * h][0] = rl[0]; bl[2 * h][1] = rl[1];
                bl[2 * h + 1][0] = rl[2]; bl[2 * h + 1][1] = rl[3];
            }
            #pragma unroll
            for (int mf = 0; mf < 2; mf++) {
                int arow = wr * 32 + mf * 16 + (q8 & 1) * 8 + r8;
                int acol = ks * 16 + (q8 >> 1) * 8;
                unsigned ah[4], al[4];
                ldsm4(ah, &sAhi[arow * KST + acol]);
                ldsm4(al, &sAlo[arow * KST + acol]);
                #pragma unroll
                for (int nf = 0; nf < 4; nf++) {
                    mma_bf16(c[mf][nf], ah, bh[nf]);   // hi*hi
                    mma_bf16(c[mf][nf], ah, bl[nf]);   // hi*lo
                    mma_bf16(c[mf][nf], al, bh[nf]);   // lo*hi
                }
            }
        }
        __syncthreads();
    }

    // ---- fused epilogue, both anchor sides ----
    float sqi[2][2]; int li[2][2];
    float sqj[4][2]; int lj[4][2];
    #pragma unroll
    for (int mf = 0; mf < 2; mf++)
        #pragma unroll
        for (int ro = 0; ro < 2; ro++) {
            int ig = i0 + wr * 32 + mf * 16 + gid + ro * 8;
            sqi[mf][ro] = g_sq[ig];
            li[mf][ro]  = L[ig];
        }
    #pragma unroll
    for (int nf = 0; nf < 4; nf++)
        #pragma unroll
        for (int co = 0; co < 2; co++) {
            int jg = j0 + wc * 32 + nf * 8 + tig * 2 + co;
            sqj[nf][co] = g_sq[jg];
            lj[nf][co]  = L[jg];
        }

    float hpi[2][2], hni[2][2], hpj[4][2], hnj[4][2];
    #pragma unroll
    for (int x = 0; x < 2; x++)
        #pragma unroll
        for (int y = 0; y < 2; y++) { hpi[x][y] = -1.0f; hni[x][y] = NEG_FILL; }
    #pragma unroll
    for (int x = 0; x < 4; x++)
        #pragma unroll
        for (int y = 0; y < 2; y++) { hpj[x][y] = -1.0f; hnj[x][y] = NEG_FILL; }

    #pragma unroll
    for (int mf = 0; mf < 2; mf++)
        #pragma unroll
        for (int ro = 0; ro < 2; ro++) {
            int ig = i0 + wr * 32 + mf * 16 + gid + ro * 8;
            #pragma unroll
            for (int nf = 0; nf < 4; nf++)
                #pragma unroll
                for (int co = 0; co < 2; co++) {
                    int jg = j0 + wc * 32 + nf * 8 + tig * 2 + co;
                    float dot = c[mf][nf][ro * 2 + co];
                    float d2 = sqi[mf][ro] + sqj[nf][co] - 2.0f * dot;
                    float d = sqrtf(fmaxf(d2, 0.0f));
                    bool same = (li[mf][ro] == lj[nf][co]);
                    bool diag = (ig == jg);
                    if (same) {
                        if (!diag) {
                            hpi[mf][ro] = fmaxf(hpi[mf][ro], d);
                            hpj[nf][co] = fmaxf(hpj[nf][co], d);
                        }
                    } else {
                        hni[mf][ro] = fminf(hni[mf][ro], d);
                        hnj[nf][co] = fminf(hnj[nf][co], d);
                    }
                }
        }

    // i-side: reduce across tig lanes
    #pragma unroll
    for (int mf = 0; mf < 2; mf++)
        #pragma unroll
        for (int ro = 0; ro < 2; ro++) {
            #pragma unroll
            for (int o = 1; o <= 2; o <<= 1) {
                hpi[mf][ro] = fmaxf(hpi[mf][ro], __shfl_xor_sync(0xffffffffu, hpi[mf][ro], o));
                hni[mf][ro] = fminf(hni[mf][ro], __shfl_xor_sync(0xffffffffu, hni[mf][ro], o));
            }
        }
    if (tig == 0) {
        #pragma unroll
        for (int mf = 0; mf < 2; mf++)
            #pragma unroll
            for (int ro = 0; ro < 2; ro++) {
                int rl = wr * 32 + mf * 16 + gid + ro * 8;
                atomicMax(&s_hpi[rl], __float_as_int(hpi[mf][ro]));
                atomicMin(&s_hni[rl], __float_as_int(hni[mf][ro]));
            }
    }

    // j-side: reduce across gid lanes
    #pragma unroll
    for (int nf = 0; nf < 4; nf++)
        #pragma unroll
        for (int co = 0; co < 2; co++) {
            #pragma unroll
            for (int o = 4; o <= 16; o <<= 1) {
                hpj[nf][co] = fmaxf(hpj[nf][co], __shfl_xor_sync(0xffffffffu, hpj[nf][co], o));
                hnj[nf][co] = fminf(hnj[nf][co], __shfl_xor_sync(0xffffffffu, hnj[nf][co], o));
            }
        }
    if (gid == 0) {
        #pragma unroll
        for (int nf = 0; nf < 4; nf++)
            #pragma unroll
            for (int co = 0; co < 2; co++) {
                int cl = wc * 32 + nf * 8 + tig * 2 + co;
                atomicMax(&s_hpj[cl], __float_as_int(hpj[nf][co]));
                atomicMin(&s_hnj[cl], __float_as_int(hnj[nf][co]));
            }
    }
    __syncthreads();

    if (tid < TM) {
        atomicMax(&g_hp[i0 + tid], s_hpi[tid]);
        atomicMin(&g_hn[i0 + tid], s_hni[tid]);
        atomicMax(&g_hp[j0 + tid], s_hpj[tid]);
        atomicMin(&g_hn[j0 + tid], s_hnj[tid]);
    }
}

// ================= finalize =================
__global__ void finalize1(float* __restrict__ out, int B) {
    __shared__ float st[32], sc[32];
    int t = threadIdx.x;
    float per = 0.0f, cnt = 0.0f;
    for (int i = t; i < B; i += blockDim.x) {
        float hp = __int_as_float(g_hp[i]);
        float hn = __int_as_float(g_hn[i]);
        if (hp >= 0.0f && hn < NEG_FILL) {
            per += fmaxf(hp - hn + MARGIN, 0.0f);
            cnt += 1.0f;
        }
    }
    #pragma unroll
    for (int o = 16; o > 0; o >>= 1) {
        per += __shfl_xor_sync(0xffffffffu, per, o);
        cnt += __shfl_xor_sync(0xffffffffu, cnt, o);
    }
    int w = t >> 5, l = t & 31;
    if (l == 0) { st[w] = per; sc[w] = cnt; }
    __syncthreads();
    if (w == 0) {
        int nw = blockDim.x >> 5;
        per = (l < nw) ? st[l] : 0.0f;
        cnt = (l < nw) ? sc[l] : 0.0f;
        #pragma unroll
        for (int o = 16; o > 0; o >>= 1) {
            per += __shfl_xor_sync(0xffffffffu, per, o);
            cnt += __shfl_xor_sync(0xffffffffu, cnt, o);
        }
        if (l == 0) out[0] = (cnt > 0.0f) ? (per / fmaxf(cnt, 1.0f)) : 0.0f;
    }
}

extern "C" void kernel_launch(void* const* d_in, const int* in_sizes, int n_in,
                              void* d_out, int out_size)
{
    const float* E = (const float*)d_in[0];
    const int* L = (const int*)d_in[1];
    const int B = in_sizes[1];
    const int D = in_sizes[0] / B;
    float* out = (float*)d_out;

    prep_kernel<<<B / 4, 256>>>(E, B, D);

    int nt = B / TM;
    int nblk = nt * (nt + 1) / 2;
    int smembytes = 2 * STAGE_B;   // 147456
    cudaFuncSetAttribute(triplet_mma_sym,
                         cudaFuncAttributeMaxDynamicSharedMemorySize, smembytes);
    triplet_mma_sym<<<nblk, 512, smembytes>>>(L, B, D, nt);

    finalize1<<<1, 1024>>>(out, B);
}

// round 7
// speedup vs baseline: 1.1359x; 1.1359x over previous
#include <cuda_runtime.h>
#include <cuda_bf16.h>
#include <cstdint>

#define MARGIN   0.3f
#define NEG_FILL 1e9f
#define MAXB 8192
#define MAXE (4096 * 256)

#define TMI 128
#define TNJ 64
#define KC 32
#define KST 40                    // 80B row stride: 16B aligned, LDSM bank-clean
#define A_T (128 * KST)           // elems per A tile
#define B_T (64 * KST)
#define OFF_AHI 0
#define OFF_ALO (A_T * 2)         // bytes
#define OFF_BHI (2 * A_T * 2)
#define OFF_BLO (2 * A_T * 2 + B_T * 2)
#define STAGE_B (2 * A_T * 2 + 2 * B_T * 2)   // 30720 bytes

// ---- device scratch (allocation-free rule) ----
__device__ __align__(16) __nv_bfloat16 g_hi[MAXE];
__device__ __align__(16) __nv_bfloat16 g_lo[MAXE];
__device__ float g_sq[MAXB];
__device__ int   g_hp[MAXB];
__device__ int   g_hn[MAXB];
__device__ unsigned int g_done;

// ================= prep: split + norms + init, one warp per row =================
__global__ void prep_kernel(const float* __restrict__ E, int B, int D) {
    const int t = threadIdx.x;
    const int lane = t & 31;
    const int row = blockIdx.x * 8 + (t >> 5);
    const float4* src = (const float4*)(E + (size_t)row * D);
    float4 x0 = src[lane];
    float4 x1 = src[lane + 32];

    uint2* ph = (uint2*)(g_hi + (size_t)row * D);
    uint2* pl = (uint2*)(g_lo + (size_t)row * D);

    float s = 0.0f;
    #pragma unroll
    for (int q = 0; q < 2; q++) {
        float4 x = q ? x1 : x0;
        int c = lane + q * 32;
        __nv_bfloat16 h0 = __float2bfloat16(x.x), h1 = __float2bfloat16(x.y);
        __nv_bfloat16 h2 = __float2bfloat16(x.z), h3 = __float2bfloat16(x.w);
        __nv_bfloat162 hv0(h0, h1), hv1(h2, h3);
        __nv_bfloat162 lv0(__float2bfloat16(x.x - __bfloat162float(h0)),
                           __float2bfloat16(x.y - __bfloat162float(h1)));
        __nv_bfloat162 lv1(__float2bfloat16(x.z - __bfloat162float(h2)),
                           __float2bfloat16(x.w - __bfloat162float(h3)));
        uint2 hu, lu;
        hu.x = *(unsigned*)&hv0; hu.y = *(unsigned*)&hv1;
        lu.x = *(unsigned*)&lv0; lu.y = *(unsigned*)&lv1;
        ph[c] = hu;
        pl[c] = lu;
        s = fmaf(x.x, x.x, fmaf(x.y, x.y, fmaf(x.z, x.z, fmaf(x.w, x.w, s))));
    }
    #pragma unroll
    for (int o = 16; o > 0; o >>= 1) s += __shfl_xor_sync(0xffffffffu, s, o);
    if (lane == 0) {
        g_sq[row] = s;
        g_hp[row] = __float_as_int(-1.0f);
        g_hn[row] = __float_as_int(NEG_FILL);
    }
    if (blockIdx.x == 0 && t == 0) g_done = 0u;
}

// ================= mma.sync helpers =================
__device__ __forceinline__ void cp16(uint32_t s, const void* g) {
    asm volatile("cp.async.cg.shared.global [%0], [%1], 16;\n" :: "r"(s), "l"(g));
}
__device__ __forceinline__ void ldsm4(unsigned r[4], const __nv_bfloat16* p) {
    unsigned a = (unsigned)__cvta_generic_to_shared(p);
    asm volatile("ldmatrix.sync.aligned.m8n8.x4.shared.b16 {%0,%1,%2,%3}, [%4];"
                 : "=r"(r[0]), "=r"(r[1]), "=r"(r[2]), "=r"(r[3]) : "r"(a));
}
__device__ __forceinline__ void mma_bf16(float c[4], const unsigned a[4], const unsigned* b) {
    asm volatile(
        "mma.sync.aligned.m16n8k16.row.col.f32.bf16.bf16.f32 "
        "{%0,%1,%2,%3}, {%4,%5,%6,%7}, {%8,%9}, {%0,%1,%2,%3};\n"
        : "+f"(c[0]), "+f"(c[1]), "+f"(c[2]), "+f"(c[3])
        : "r"(a[0]), "r"(a[1]), "r"(a[2]), "r"(a[3]), "r"(b[0]), "r"(b[1]));
}

// ================= main: 256-thread, TM=128 x TN=64, occ-3 =================
extern __shared__ __nv_bfloat16 dynsmem[];

__global__ void __launch_bounds__(256, 3)
triplet_mma_sym(const int* __restrict__ L, float* __restrict__ out,
                int B, int D, int ntj, int nblk)
{
    const int tid = threadIdx.x;
    const int lane = tid & 31;
    const int w = tid >> 5;
    const int wr = w >> 1, wc = w & 1;      // 4x2 warp grid, 32x32 warp tiles
    const int gid = lane >> 2, tig = lane & 3;
    const int q8 = lane >> 3, r8 = lane & 7;

    // decode (ib, jb): jb >= 2*ib, cum(ib) = ib*(ntj+1-ib)
    int u = blockIdx.x;
    float nt1 = (float)(ntj + 1);
    int ib = (int)((nt1 - sqrtf(fmaxf(nt1 * nt1 - 4.0f * (float)u, 0.0f))) * 0.5f);
    while (ib > 0 && ib * (ntj + 1 - ib) > u) ib--;
    while ((ib + 1) * (ntj - ib) <= u) ib++;
    int jb = 2 * ib + (u - ib * (ntj + 1 - ib));
    const int i0 = ib * TMI, j0 = jb * TNJ;

    __shared__ int s_hpi[TMI], s_hni[TMI], s_hpj[TNJ], s_hnj[TNJ];
    __shared__ bool s_last;
    if (tid < TMI) { s_hpi[tid] = __float_as_int(-1.0f); s_hni[tid] = __float_as_int(NEG_FILL); }
    if (tid < TNJ) { s_hpj[tid] = __float_as_int(-1.0f); s_hnj[tid] = __float_as_int(NEG_FILL); }

    float c[2][4][4];
    #pragma unroll
    for (int mf = 0; mf < 2; mf++)
        #pragma unroll
        for (int nf = 0; nf < 4; nf++)
            #pragma unroll
            for (int r = 0; r < 4; r++) c[mf][nf][r] = 0.0f;

    const uint32_t dsm_a = (uint32_t)__cvta_generic_to_shared(dynsmem);

    auto issue = [&](int kc, int st) {
        const uint32_t sb = dsm_a + st * STAGE_B;
        // A tiles: 512 chunk-slots, 2 per thread (hi+lo each)
        #pragma unroll
        for (int s = 0; s < 2; s++) {
            int idx = tid + s * 256;
            int row = idx >> 2, ch = idx & 3;
            size_t g = (size_t)(i0 + row) * D + kc * KC + ch * 8;
            uint32_t o = (uint32_t)(row * 80 + ch * 16);
            cp16(sb + OFF_AHI + o, g_hi + g);
            cp16(sb + OFF_ALO + o, g_lo + g);
        }
        // B tiles: 256 chunk-slots, 1 per thread (hi+lo each)
        {
            int row = tid >> 2, ch = tid & 3;
            size_t g = (size_t)(j0 + row) * D + kc * KC + ch * 8;
            uint32_t o = (uint32_t)(row * 80 + ch * 16);
            cp16(sb + OFF_BHI + o, g_hi + g);
            cp16(sb + OFF_BLO + o, g_lo + g);
        }
        asm volatile("cp.async.commit_group;");
    };

    issue(0, 0);

    const int NKC = D / KC;   // 8
    for (int kc = 0; kc < NKC; kc++) {
        const int cur = kc & 1;
        if (kc + 1 < NKC) {
            issue(kc + 1, cur ^ 1);
            asm volatile("cp.async.wait_group 1;");
        } else {
            asm volatile("cp.async.wait_group 0;");
        }
        __syncthreads();

        const __nv_bfloat16* sAhi = dynsmem + (cur * STAGE_B) / 2;
        const __nv_bfloat16* sAlo = sAhi + A_T;
        const __nv_bfloat16* sBhi = sAlo + A_T;
        const __nv_bfloat16* sBlo = sBhi + B_T;

        #pragma unroll
        for (int ks = 0; ks < KC / 16; ks++) {
            unsigned bh[4][2], bl[4][2];
            #pragma unroll
            for (int h = 0; h < 2; h++) {
                int brow = wc * 32 + (2 * h + (q8 >> 1)) * 8 + r8;
                int bcol = ks * 16 + (q8 & 1) * 8;
                unsigned rh[4], rl[4];
                ldsm4(rh, &sBhi[brow * KST + bcol]);
                ldsm4(rl, &sBlo[brow * KST + bcol]);
                bh[2 * h][0] = rh[0]; bh[2 * h][1] = rh[1];
                bh[2 * h + 1][0] = rh[2]; bh[2 * h + 1][1] = rh[3];
                bl[2 * h][0] = rl[0]; bl[2 * h][1] = rl[1];
                bl[2 * h + 1][0] = rl[2]; bl[2 * h + 1][1] = rl[3];
            }
            #pragma unroll
            for (int mf = 0; mf < 2; mf++) {
                int arow = wr * 32 + mf * 16 + (q8 & 1) * 8 + r8;
                int acol = ks * 16 + (q8 >> 1) * 8;
                unsigned ah[4], al[4];
                ldsm4(ah, &sAhi[arow * KST + acol]);
                ldsm4(al, &sAlo[arow * KST + acol]);
                #pragma unroll
                for (int nf = 0; nf < 4; nf++) {
                    mma_bf16(c[mf][nf], ah, bh[nf]);   // hi*hi
                    mma_bf16(c[mf][nf], ah, bl[nf]);   // hi*lo
                    mma_bf16(c[mf][nf], al, bh[nf]);   // lo*hi
                }
            }
        }
        __syncthreads();
    }

    // ---- fused epilogue, both anchor sides ----
    float sqi[2][2]; int li[2][2];
    float sqj[4][2]; int lj[4][2];
    #pragma unroll
    for (int mf = 0; mf < 2; mf++)
        #pragma unroll
        for (int ro = 0; ro < 2; ro++) {
            int ig = i0 + wr * 32 + mf * 16 + gid + ro * 8;
            sqi[mf][ro] = g_sq[ig];
            li[mf][ro]  = L[ig];
        }
    #pragma unroll
    for (int nf = 0; nf < 4; nf++)
        #pragma unroll
        for (int co = 0; co < 2; co++) {
            int jg = j0 + wc * 32 + nf * 8 + tig * 2 + co;
            sqj[nf][co] = g_sq[jg];
            lj[nf][co]  = L[jg];
        }

    float hpi[2][2], hni[2][2], hpj[4][2], hnj[4][2];
    #pragma unroll
    for (int x = 0; x < 2; x++)
        #pragma unroll
        for (int y = 0; y < 2; y++) { hpi[x][y] = -1.0f; hni[x][y] = NEG_FILL; }
    #pragma unroll
    for (int x = 0; x < 4; x++)
        #pragma unroll
        for (int y = 0; y < 2; y++) { hpj[x][y] = -1.0f; hnj[x][y] = NEG_FILL; }

    #pragma unroll
    for (int mf = 0; mf < 2; mf++)
        #pragma unroll
        for (int ro = 0; ro < 2; ro++) {
            int ig = i0 + wr * 32 + mf * 16 + gid + ro * 8;
            #pragma unroll
            for (int nf = 0; nf < 4; nf++)
                #pragma unroll
                for (int co = 0; co < 2; co++) {
                    int jg = j0 + wc * 32 + nf * 8 + tig * 2 + co;
                    float dot = c[mf][nf][ro * 2 + co];
                    float d2 = sqi[mf][ro] + sqj[nf][co] - 2.0f * dot;
                    float d = sqrtf(fmaxf(d2, 0.0f));
                    bool same = (li[mf][ro] == lj[nf][co]);
                    bool diag = (ig == jg);
                    if (same) {
                        if (!diag) {
                            hpi[mf][ro] = fmaxf(hpi[mf][ro], d);
                            hpj[nf][co] = fmaxf(hpj[nf][co], d);
                        }
                    } else {
                        hni[mf][ro] = fminf(hni[mf][ro], d);
                        hnj[nf][co] = fminf(hnj[nf][co], d);
                    }
                }
        }

    // i-side: reduce across tig lanes
    #pragma unroll
    for (int mf = 0; mf < 2; mf++)
        #pragma unroll
        for (int ro = 0; ro < 2; ro++) {
            #pragma unroll
            for (int o = 1; o <= 2; o <<= 1) {
                hpi[mf][ro] = fmaxf(hpi[mf][ro], __shfl_xor_sync(0xffffffffu, hpi[mf][ro], o));
                hni[mf][ro] = fminf(hni[mf][ro], __shfl_xor_sync(0xffffffffu, hni[mf][ro], o));
            }
        }
    if (tig == 0) {
        #pragma unroll
        for (int mf = 0; mf < 2; mf++)
            #pragma unroll
            for (int ro = 0; ro < 2; ro++) {
                int rl = wr * 32 + mf * 16 + gid + ro * 8;
                atomicMax(&s_hpi[rl], __float_as_int(hpi[mf][ro]));
                atomicMin(&s_hni[rl], __float_as_int(hni[mf][ro]));
            }
    }

    // j-side: reduce across gid lanes
    #pragma unroll
    for (int nf = 0; nf < 4; nf++)
        #pragma unroll
        for (int co = 0; co < 2; co++) {
            #pragma unroll
            for (int o = 4; o <= 16; o <<= 1) {
                hpj[nf][co] = fmaxf(hpj[nf][co], __shfl_xor_sync(0xffffffffu, hpj[nf][co], o));
                hnj[nf][co] = fminf(hnj[nf][co], __shfl_xor_sync(0xffffffffu, hnj[nf][co], o));
            }
        }
    if (gid == 0) {
        #pragma unroll
        for (int nf = 0; nf < 4; nf++)
            #pragma unroll
            for (int co = 0; co < 2; co++) {
                int cl = wc * 32 + nf * 8 + tig * 2 + co;
                atomicMax(&s_hpj[cl], __float_as_int(hpj[nf][co]));
                atomicMin(&s_hnj[cl], __float_as_int(hnj[nf][co]));
            }
    }
    __syncthreads();

    if (tid < TMI) {
        atomicMax(&g_hp[i0 + tid], s_hpi[tid]);
        atomicMin(&g_hn[i0 + tid], s_hni[tid]);
    }
    if (tid < TNJ) {
        atomicMax(&g_hp[j0 + tid], s_hpj[tid]);
        atomicMin(&g_hn[j0 + tid], s_hnj[tid]);
    }

    // ---- last-CTA finalize ----
    __threadfence();
    if (tid == 0) s_last = (atomicAdd(&g_done, 1u) == (unsigned)(nblk - 1));
    __syncthreads();
    if (!s_last) return;

    {
        __shared__ float st[8], sc[8];
        float per = 0.0f, cnt = 0.0f;
        for (int i = tid; i < B; i += 256) {
            float hp = __int_as_float(__ldcg(&g_hp[i]));
            float hn = __int_as_float(__ldcg(&g_hn[i]));
            if (hp >= 0.0f && hn < NEG_FILL) {
                per += fmaxf(hp - hn + MARGIN, 0.0f);
                cnt += 1.0f;
            }
        }
        #pragma unroll
        for (int o = 16; o > 0; o >>= 1) {
            per += __shfl_xor_sync(0xffffffffu, per, o);
            cnt += __shfl_xor_sync(0xffffffffu, cnt, o);
        }
        if (lane == 0) { st[w] = per; sc[w] = cnt; }
        __syncthreads();
        if (tid == 0) {
            float tp = 0.0f, tc = 0.0f;
            #pragma unroll
            for (int i = 0; i < 8; i++) { tp += st[i]; tc += sc[i]; }
            out[0] = (tc > 0.0f) ? (tp / fmaxf(tc, 1.0f)) : 0.0f;
        }
    }
}

extern "C" void kernel_launch(void* const* d_in, const int* in_sizes, int n_in,
                              void* d_out, int out_size)
{
    const float* E = (const float*)d_in[0];
    const int* L = (const int*)d_in[1];
    const int B = in_sizes[1];
    const int D = in_sizes[0] / B;
    float* out = (float*)d_out;

    prep_kernel<<<B / 8, 256>>>(E, B, D);

    int nti = B / TMI;               // 32
    int ntj = B / TNJ;               // 64
    int nblk = nti * (ntj + 1 - nti) + nti * (nti - 1);  // = sum(ntj - 2*ib) ; for 32/64: 1056
    // exact: sum_{ib=0}^{nti-1} (ntj - 2*ib) = nti*ntj - nti*(nti-1)
    nblk = nti * ntj - nti * (nti - 1);

    int smembytes = 2 * STAGE_B;     // 61440
    cudaFuncSetAttribute(triplet_mma_sym,
                         cudaFuncAttributeMaxDynamicSharedMemorySize, smembytes);
    triplet_mma_sym<<<nblk, 256, smembytes>>>(L, out, B, D, ntj, nblk);
}

// round 8
// speedup vs baseline: 1.8480x; 1.6269x over previous
#include <cuda_runtime.h>
#include <cuda_fp16.h>
#include <cstdint>

#define MARGIN   0.3f
#define NEG_FILL 1e9f
#define MAXB 8192
#define MAXE (4096 * 256)

#define TM 128
#define KC 64
#define KST 72                     // row stride elems (144B)
#define TILE_BYTES (128 * 144)     // 18432
#define STAGE_BYTES (2 * TILE_BYTES)

// ---- device scratch (allocation-free rule) ----
__device__ __align__(16) __half g_h[MAXE];
__device__ float g_sq[MAXB];
__device__ int   g_hp[MAXB];
__device__ int   g_hn[MAXB];
__device__ unsigned int g_done;

// ================= prep: fp32->fp16 + norms + init, one warp per row =================
__global__ void prep_kernel(const float* __restrict__ E, int B, int D) {
    const int t = threadIdx.x;
    const int lane = t & 31;
    const int row = blockIdx.x * 8 + (t >> 5);
    const float4* src = (const float4*)(E + (size_t)row * D);
    uint2* ph = (uint2*)(g_h + (size_t)row * D);

    float s = 0.0f;
    #pragma unroll
    for (int q = 0; q < 2; q++) {
        int c = lane + q * 32;
        float4 x = src[c];
        __half2 h0 = __floats2half2_rn(x.x, x.y);
        __half2 h1 = __floats2half2_rn(x.z, x.w);
        uint2 hu;
        hu.x = *(unsigned*)&h0; hu.y = *(unsigned*)&h1;
        ph[c] = hu;
        s = fmaf(x.x, x.x, fmaf(x.y, x.y, fmaf(x.z, x.z, fmaf(x.w, x.w, s))));
    }
    #pragma unroll
    for (int o = 16; o > 0; o >>= 1) s += __shfl_xor_sync(0xffffffffu, s, o);
    if (lane == 0) {
        g_sq[row] = s;
        g_hp[row] = __float_as_int(-1.0f);
        g_hn[row] = __float_as_int(NEG_FILL);
    }
    if (blockIdx.x == 0 && t == 0) g_done = 0u;
}

// ================= mma.sync helpers =================
__device__ __forceinline__ void cp16(uint32_t s, const void* g) {
    asm volatile("cp.async.cg.shared.global [%0], [%1], 16;\n" :: "r"(s), "l"(g));
}
__device__ __forceinline__ void ldsm4(unsigned r[4], const __half* p) {
    unsigned a = (unsigned)__cvta_generic_to_shared(p);
    asm volatile("ldmatrix.sync.aligned.m8n8.x4.shared.b16 {%0,%1,%2,%3}, [%4];"
                 : "=r"(r[0]), "=r"(r[1]), "=r"(r[2]), "=r"(r[3]) : "r"(a));
}
__device__ __forceinline__ void mma_fp16(float c[4], const unsigned a[4], const unsigned* b) {
    asm volatile(
        "mma.sync.aligned.m16n8k16.row.col.f32.f16.f16.f32 "
        "{%0,%1,%2,%3}, {%4,%5,%6,%7}, {%8,%9}, {%0,%1,%2,%3};\n"
        : "+f"(c[0]), "+f"(c[1]), "+f"(c[2]), "+f"(c[3])
        : "r"(a[0]), "r"(a[1]), "r"(a[2]), "r"(a[3]), "r"(b[0]), "r"(b[1]));
}

// ================= main: 128x128 symmetric tiles, single fp16 MMA =================
extern __shared__ __half dynsmem[];

__global__ void __launch_bounds__(256, 2)
triplet_mma_sym(const int* __restrict__ L, float* __restrict__ out,
                int B, int D, int nt, int nblk)
{
    const int tid = threadIdx.x;
    const int lane = tid & 31;
    const int w = tid >> 5;
    const int wr = w >> 2, wc = w & 3;       // 2x4 warp grid, 64x32 warp tiles
    const int gid = lane >> 2, tig = lane & 3;
    const int q8 = lane >> 3, r8 = lane & 7;

    // decode upper-triangular (bi <= bj) tile pair
    int u = blockIdx.x;
    float ntf = (float)nt + 0.5f;
    int bi = (int)(ntf - sqrtf(fmaxf(ntf * ntf - 2.0f * (float)u, 0.0f)));
    while (bi > 0 && (bi * nt - bi * (bi - 1) / 2) > u) bi--;
    while (((bi + 1) * nt - (bi + 1) * bi / 2) <= u) bi++;
    int bj = bi + (u - (bi * nt - bi * (bi - 1) / 2));
    const int i0 = bi * TM, j0 = bj * TM;

    __shared__ int s_hpi[TM], s_hni[TM], s_hpj[TM], s_hnj[TM];
    __shared__ bool s_last;
    if (tid < TM) {
        s_hpi[tid] = __float_as_int(-1.0f); s_hni[tid] = __float_as_int(NEG_FILL);
        s_hpj[tid] = __float_as_int(-1.0f); s_hnj[tid] = __float_as_int(NEG_FILL);
    }

    float c[4][4][4];
    #pragma unroll
    for (int mf = 0; mf < 4; mf++)
        #pragma unroll
        for (int nf = 0; nf < 4; nf++)
            #pragma unroll
            for (int r = 0; r < 4; r++) c[mf][nf][r] = 0.0f;

    const uint32_t dsm_a = (uint32_t)__cvta_generic_to_shared(dynsmem);

    // fill one stage: tiles {A, B}, 128 rows x 64 fp16 (128B data, 144B stride)
    auto issue = [&](int kc, int st) {
        const uint32_t sb = dsm_a + st * STAGE_BYTES;
        const int ch = tid & 7;            // 16B chunk in 128B row
        const int r0 = tid >> 3;           // 0..31
        #pragma unroll
        for (int q = 0; q < 8; q++) {
            const int tile = q >> 2;       // 0..1 (A, B)
            const int r = (q & 3) * 32 + r0;
            const int rowg = (tile == 0) ? (i0 + r) : (j0 + r);
            const void* gsrc = g_h + (size_t)rowg * D + kc * KC + ch * 8;
            uint32_t dst = sb + tile * TILE_BYTES + (uint32_t)(r * 144 + ch * 16);
            cp16(dst, gsrc);
        }
        asm volatile("cp.async.commit_group;");
    };

    issue(0, 0);

    const int NKC = D / KC;   // 4
    for (int kc = 0; kc < NKC; kc++) {
        const int cur = kc & 1;
        if (kc + 1 < NKC) {
            issue(kc + 1, cur ^ 1);
            asm volatile("cp.async.wait_group 1;");
        } else {
            asm volatile("cp.async.wait_group 0;");
        }
        __syncthreads();

        const __half* sA = dynsmem + (cur * STAGE_BYTES) / 2;
        const __half* sB = sA + TILE_BYTES / 2;

        #pragma unroll
        for (int ks = 0; ks < KC / 16; ks++) {
            // B fragments: 2 ldsm4, each covers 2 nf groups
            unsigned bf[4][2];
            #pragma unroll
            for (int h = 0; h < 2; h++) {
                int brow = wc * 32 + (2 * h + (q8 >> 1)) * 8 + r8;
                int bcol = ks * 16 + (q8 & 1) * 8;
                unsigned rb[4];
                ldsm4(rb, &sB[brow * KST + bcol]);
                bf[2 * h][0] = rb[0]; bf[2 * h][1] = rb[1];
                bf[2 * h + 1][0] = rb[2]; bf[2 * h + 1][1] = rb[3];
            }
            #pragma unroll
            for (int mf = 0; mf < 4; mf++) {
                int arow = wr * 64 + mf * 16 + (q8 & 1) * 8 + r8;
                int acol = ks * 16 + (q8 >> 1) * 8;
                unsigned af[4];
                ldsm4(af, &sA[arow * KST + acol]);
                #pragma unroll
                for (int nf = 0; nf < 4; nf++)
                    mma_fp16(c[mf][nf], af, bf[nf]);
            }
        }
        __syncthreads();
    }

    // ---- fused epilogue, both anchor sides ----
    float sqi[4][2]; int li[4][2];
    float sqj[4][2]; int lj[4][2];
    #pragma unroll
    for (int mf = 0; mf < 4; mf++)
        #pragma unroll
        for (int ro = 0; ro < 2; ro++) {
            int ig = i0 + wr * 64 + mf * 16 + gid + ro * 8;
            sqi[mf][ro] = g_sq[ig];
            li[mf][ro]  = L[ig];
        }
    #pragma unroll
    for (int nf = 0; nf < 4; nf++)
        #pragma unroll
        for (int co = 0; co < 2; co++) {
            int jg = j0 + wc * 32 + nf * 8 + tig * 2 + co;
            sqj[nf][co] = g_sq[jg];
            lj[nf][co]  = L[jg];
        }

    float hpi[4][2], hni[4][2], hpj[4][2], hnj[4][2];
    #pragma unroll
    for (int x = 0; x < 4; x++)
        #pragma unroll
        for (int y = 0; y < 2; y++) {
            hpi[x][y] = -1.0f; hni[x][y] = NEG_FILL;
            hpj[x][y] = -1.0f; hnj[x][y] = NEG_FILL;
        }

    #pragma unroll
    for (int mf = 0; mf < 4; mf++)
        #pragma unroll
        for (int ro = 0; ro < 2; ro++) {
            int ig = i0 + wr * 64 + mf * 16 + gid + ro * 8;
            #pragma unroll
            for (int nf = 0; nf < 4; nf++)
                #pragma unroll
                for (int co = 0; co < 2; co++) {
                    int jg = j0 + wc * 32 + nf * 8 + tig * 2 + co;
                    float dot = c[mf][nf][ro * 2 + co];
                    float d2 = sqi[mf][ro] + sqj[nf][co] - 2.0f * dot;
                    float d = sqrtf(fmaxf(d2, 0.0f));
                    bool same = (li[mf][ro] == lj[nf][co]);
                    bool diag = (ig == jg);
                    if (same) {
                        if (!diag) {
                            hpi[mf][ro] = fmaxf(hpi[mf][ro], d);
                            hpj[nf][co] = fmaxf(hpj[nf][co], d);
                        }
                    } else {
                        hni[mf][ro] = fminf(hni[mf][ro], d);
                        hnj[nf][co] = fminf(hnj[nf][co], d);
                    }
                }
        }

    // i-side: reduce across tig lanes
    #pragma unroll
    for (int mf = 0; mf < 4; mf++)
        #pragma unroll
        for (int ro = 0; ro < 2; ro++) {
            #pragma unroll
            for (int o = 1; o <= 2; o <<= 1) {
                hpi[mf][ro] = fmaxf(hpi[mf][ro], __shfl_xor_sync(0xffffffffu, hpi[mf][ro], o));
                hni[mf][ro] = fminf(hni[mf][ro], __shfl_xor_sync(0xffffffffu, hni[mf][ro], o));
            }
        }
    if (tig == 0) {
        #pragma unroll
        for (int mf = 0; mf < 4; mf++)
            #pragma unroll
            for (int ro = 0; ro < 2; ro++) {
                int rl = wr * 64 + mf * 16 + gid + ro * 8;
                atomicMax(&s_hpi[rl], __float_as_int(hpi[mf][ro]));
                atomicMin(&s_hni[rl], __float_as_int(hni[mf][ro]));
            }
    }

    // j-side: reduce across gid lanes
    #pragma unroll
    for (int nf = 0; nf < 4; nf++)
        #pragma unroll
        for (int co = 0; co < 2; co++) {
            #pragma unroll
            for (int o = 4; o <= 16; o <<= 1) {
                hpj[nf][co] = fmaxf(hpj[nf][co], __shfl_xor_sync(0xffffffffu, hpj[nf][co], o));
                hnj[nf][co] = fminf(hnj[nf][co], __shfl_xor_sync(0xffffffffu, hnj[nf][co], o));
            }
        }
    if (gid == 0) {
        #pragma unroll
        for (int nf = 0; nf < 4; nf++)
            #pragma unroll
            for (int co = 0; co < 2; co++) {
                int cl = wc * 32 + nf * 8 + tig * 2 + co;
                atomicMax(&s_hpj[cl], __float_as_int(hpj[nf][co]));
                atomicMin(&s_hnj[cl], __float_as_int(hnj[nf][co]));
            }
    }
    __syncthreads();

    if (tid < TM) {
        atomicMax(&g_hp[i0 + tid], s_hpi[tid]);
        atomicMin(&g_hn[i0 + tid], s_hni[tid]);
        atomicMax(&g_hp[j0 + tid], s_hpj[tid]);
        atomicMin(&g_hn[j0 + tid], s_hnj[tid]);
    }

    // ---- last-CTA finalize ----
    __threadfence();
    if (tid == 0) s_last = (atomicAdd(&g_done, 1u) == (unsigned)(nblk - 1));
    __syncthreads();
    if (!s_last) return;

    {
        __shared__ float st[8], sc[8];
        float per = 0.0f, cnt = 0.0f;
        for (int i = tid; i < B; i += 256) {
            float hp = __int_as_float(__ldcg(&g_hp[i]));
            float hn = __int_as_float(__ldcg(&g_hn[i]));
            if (hp >= 0.0f && hn < NEG_FILL) {
                per += fmaxf(hp - hn + MARGIN, 0.0f);
                cnt += 1.0f;
            }
        }
        #pragma unroll
        for (int o = 16; o > 0; o >>= 1) {
            per += __shfl_xor_sync(0xffffffffu, per, o);
            cnt += __shfl_xor_sync(0xffffffffu, cnt, o);
        }
        if (lane == 0) { st[w] = per; sc[w] = cnt; }
        __syncthreads();
        if (tid == 0) {
            float tp = 0.0f, tc = 0.0f;
            #pragma unroll
            for (int i = 0; i < 8; i++) { tp += st[i]; tc += sc[i]; }
            out[0] = (tc > 0.0f) ? (tp / fmaxf(tc, 1.0f)) : 0.0f;
        }
    }
}

extern "C" void kernel_launch(void* const* d_in, const int* in_sizes, int n_in,
                              void* d_out, int out_size)
{
    const float* E = (const float*)d_in[0];
    const int* L = (const int*)d_in[1];
    const int B = in_sizes[1];
    const int D = in_sizes[0] / B;
    float* out = (float*)d_out;

    prep_kernel<<<B / 8, 256>>>(E, B, D);

    int nt = B / TM;                       // 32
    int nblk = nt * (nt + 1) / 2;          // 528
    int smembytes = 2 * STAGE_BYTES;       // 73728
    cudaFuncSetAttribute(triplet_mma_sym,
                         cudaFuncAttributeMaxDynamicSharedMemorySize, smembytes);
    triplet_mma_sym<<<nblk, 256, smembytes>>>(L, out, B, D, nt, nblk);
}